// round 1
// baseline (speedup 1.0000x reference)
#include <cuda_runtime.h>
#include <cuda_bf16.h>
#include <mma.h>

using namespace nvcuda;

#define BB 4
#define NN 4096
#define DIMV 128
#define DE 512
#define TOT (BB * NN)          // 16384 rows
#define CHUNK 64
#define NCHUNK (NN / CHUNK)    // 64

// Scratch (allocation-free: __device__ globals)
__device__ float g_sh[(size_t)TOT * 1024];   // per row: [0,512)=s, [512,1024)=h (raw, post-bias)
__device__ float g_o[(size_t)TOT * DE];      // gated aggregation, input to final GEMM
__device__ float g_part[BB * NCHUNK * DE];   // chunk partial sums -> exclusive offsets

#define SAP 68   // smem pitch (floats)

// ---------------------------------------------------------------------------
// Generic tf32 wmma GEMM:  out[m, j] = sum_k A[m,k] * W[j,k] + bias[j]
// W is row-major [Ntot, K]. Supports a split weight (j >= splitJ uses W1/bias1).
// Tile: 64x64 per block (256 threads, 8 warps of 16x32), BK=64.
// ---------------------------------------------------------------------------
__global__ __launch_bounds__(256) void gemm_tf32_kernel(
    const float* __restrict__ A, int lda,
    const float* __restrict__ W0, const float* __restrict__ bias0,
    const float* __restrict__ W1, const float* __restrict__ bias1,
    int splitJ, int K,
    float* __restrict__ out, int ldo)
{
    __shared__ float sa[64 * SAP];
    __shared__ float sb[64 * SAP];

    const int m0 = blockIdx.x * 64;
    const int j0 = blockIdx.y * 64;

    const float* W = W0;
    const float* bias = bias0;
    int jw = j0;
    if (j0 >= splitJ) { W = W1; bias = bias1; jw = j0 - splitJ; }

    const int tid = threadIdx.x;
    const int warp = tid >> 5;
    const int wm = (warp & 3) * 16;   // warp row offset in tile
    const int wn = (warp >> 2) * 32;  // warp col offset in tile

    wmma::fragment<wmma::accumulator, 16, 16, 8, float> c0, c1;
    wmma::fill_fragment(c0, 0.0f);
    wmma::fill_fragment(c1, 0.0f);

    for (int kb = 0; kb < K; kb += 64) {
        // Load A tile 64x64 (vectorized, coalesced)
        #pragma unroll
        for (int i = 0; i < 4; i++) {
            int idx = tid + i * 256;        // 0..1023 float4 slots
            int r = idx >> 4;               // 0..63
            int c4 = (idx & 15) << 2;       // 0..60 step 4
            float4 v = *reinterpret_cast<const float4*>(
                &A[(size_t)(m0 + r) * lda + kb + c4]);
            *reinterpret_cast<float4*>(&sa[r * SAP + c4]) = v;
        }
        // Load B tile: sb[j][k] = W[(jw+j)*K + kb + k]
        #pragma unroll
        for (int i = 0; i < 4; i++) {
            int idx = tid + i * 256;
            int r = idx >> 4;
            int c4 = (idx & 15) << 2;
            float4 v = *reinterpret_cast<const float4*>(
                &W[(size_t)(jw + r) * K + kb + c4]);
            *reinterpret_cast<float4*>(&sb[r * SAP + c4]) = v;
        }
        __syncthreads();

        #pragma unroll
        for (int kk = 0; kk < 64; kk += 8) {
            wmma::fragment<wmma::matrix_a, 16, 16, 8, wmma::precision::tf32, wmma::row_major> af;
            wmma::fragment<wmma::matrix_b, 16, 16, 8, wmma::precision::tf32, wmma::col_major> bf0, bf1;
            wmma::load_matrix_sync(af, &sa[wm * SAP + kk], SAP);
            wmma::load_matrix_sync(bf0, &sb[wn * SAP + kk], SAP);
            wmma::load_matrix_sync(bf1, &sb[(wn + 16) * SAP + kk], SAP);
            #pragma unroll
            for (int t = 0; t < af.num_elements; t++)  af.x[t]  = wmma::__float_to_tf32(af.x[t]);
            #pragma unroll
            for (int t = 0; t < bf0.num_elements; t++) bf0.x[t] = wmma::__float_to_tf32(bf0.x[t]);
            #pragma unroll
            for (int t = 0; t < bf1.num_elements; t++) bf1.x[t] = wmma::__float_to_tf32(bf1.x[t]);
            wmma::mma_sync(c0, af, bf0, c0);
            wmma::mma_sync(c1, af, bf1, c1);
        }
        __syncthreads();
    }

    // Epilogue: stage through smem, add bias, coalesced global store
    wmma::store_matrix_sync(&sa[wm * SAP + wn],      c0, SAP, wmma::mem_row_major);
    wmma::store_matrix_sync(&sa[wm * SAP + wn + 16], c1, SAP, wmma::mem_row_major);
    __syncthreads();
    #pragma unroll
    for (int i = 0; i < 16; i++) {
        int idx = tid + i * 256;   // 0..4095
        int r = idx >> 6;
        int c = idx & 63;
        out[(size_t)(m0 + r) * ldo + j0 + c] = sa[r * SAP + c] + bias[jw + c];
    }
}

// ---------------------------------------------------------------------------
// Elementwise helpers
// ---------------------------------------------------------------------------
__device__ __forceinline__ float gelu_exact(float x) {
    return 0.5f * x * (1.0f + erff(x * 0.70710678118654752f));
}
__device__ __forceinline__ float sigmoid_f(float x) {
    return 1.0f / (1.0f + expf(-x));
}

// ---------------------------------------------------------------------------
// Pass A: per-chunk sums of the gelu-combined h.
// Thread d in [0,256) handles channel pair (d, d+256):
//   hc_lo = gelu(h[d]),  hc_hi = gelu(h[d]) * gelu(h[d+256])
// ---------------------------------------------------------------------------
__global__ __launch_bounds__(256) void chunk_sum_kernel() {
    const int b  = blockIdx.x / NCHUNK;
    const int ch = blockIdx.x % NCHUNK;
    const int d  = threadIdx.x;  // 0..255

    float s_lo = 0.0f, s_hi = 0.0f;
    size_t base = ((size_t)(b * NN + ch * CHUNK)) * 1024 + 512;
    for (int r = 0; r < CHUNK; r++) {
        float x1 = g_sh[base + (size_t)r * 1024 + d];
        float x2 = g_sh[base + (size_t)r * 1024 + 256 + d];
        float g1 = gelu_exact(x1);
        s_lo += g1;
        s_hi += g1 * gelu_exact(x2);
    }
    int pb = (b * NCHUNK + ch) * DE;
    g_part[pb + d]       = s_lo;
    g_part[pb + 256 + d] = s_hi;
}

// ---------------------------------------------------------------------------
// Exclusive scan of chunk partials along the chunk axis (tiny).
// ---------------------------------------------------------------------------
__global__ __launch_bounds__(256) void scan_part_kernel() {
    int t = blockIdx.x * blockDim.x + threadIdx.x;  // 0..2047
    int b = t / DE;
    int d = t % DE;
    float run = 0.0f;
    for (int c = 0; c < NCHUNK; c++) {
        int idx = (b * NCHUNK + c) * DE + d;
        float v = g_part[idx];
        g_part[idx] = run;
        run += v;
    }
}

// ---------------------------------------------------------------------------
// Pass B: within-chunk inclusive scan with exclusive offset, then
//   o = sigmoid(s) * agg / (m+1 + 1e-7)
// ---------------------------------------------------------------------------
__global__ __launch_bounds__(256) void scan_apply_kernel() {
    const int b  = blockIdx.x / NCHUNK;
    const int ch = blockIdx.x % NCHUNK;
    const int d  = threadIdx.x;  // 0..255

    int pb = (b * NCHUNK + ch) * DE;
    float run_lo = g_part[pb + d];
    float run_hi = g_part[pb + 256 + d];

    for (int r = 0; r < CHUNK; r++) {
        int n = ch * CHUNK + r;
        size_t row = (size_t)(b * NN + n);
        float x1 = g_sh[row * 1024 + 512 + d];
        float x2 = g_sh[row * 1024 + 768 + d];
        float g1 = gelu_exact(x1);
        run_lo += g1;
        run_hi += g1 * gelu_exact(x2);

        float rec = 1.0f / ((float)(n + 1) + 1e-7f);
        float s1 = g_sh[row * 1024 + d];
        float s2 = g_sh[row * 1024 + 256 + d];
        g_o[row * DE + d]       = sigmoid_f(s1) * run_lo * rec;
        g_o[row * DE + 256 + d] = sigmoid_f(s2) * run_hi * rec;
    }
}

// ---------------------------------------------------------------------------
// Launcher
// Inputs (metadata order): xq, mask(unused: causal tril by construction),
//                          W_se, b_se, W_po, b_po, W_ag, b_ag
// ---------------------------------------------------------------------------
extern "C" void kernel_launch(void* const* d_in, const int* in_sizes, int n_in,
                              void* d_out, int out_size) {
    const float* xq   = (const float*)d_in[0];
    const float* W_se = (const float*)d_in[2];
    const float* b_se = (const float*)d_in[3];
    const float* W_po = (const float*)d_in[4];
    const float* b_po = (const float*)d_in[5];
    const float* W_ag = (const float*)d_in[6];
    const float* b_ag = (const float*)d_in[7];
    float* out = (float*)d_out;

    float* sh_ptr = nullptr;
    float* o_ptr  = nullptr;
    cudaGetSymbolAddress((void**)&sh_ptr, g_sh);
    cudaGetSymbolAddress((void**)&o_ptr, g_o);

    // GEMM1+2 fused: [16384,128] x [1024,128]^T -> s|h
    {
        dim3 grid(TOT / 64, 1024 / 64);
        gemm_tf32_kernel<<<grid, 256>>>(
            xq, DIMV,
            W_se, b_se, W_po, b_po,
            /*splitJ=*/DE, /*K=*/DIMV,
            sh_ptr, /*ldo=*/1024);
    }

    chunk_sum_kernel<<<BB * NCHUNK, 256>>>();
    scan_part_kernel<<<(BB * DE) / 256, 256>>>();
    scan_apply_kernel<<<BB * NCHUNK, 256>>>();

    // GEMM3: [16384,512] x [128,512]^T -> out
    {
        dim3 grid(TOT / 64, DIMV / 64);
        gemm_tf32_kernel<<<grid, 256>>>(
            o_ptr, DE,
            W_ag, b_ag, W_ag, b_ag,
            /*splitJ=*/1 << 30, /*K=*/DE,
            out, /*ldo=*/DIMV);
    }
}

// round 2
// speedup vs baseline: 1.2044x; 1.2044x over previous
#include <cuda_runtime.h>
#include <cuda_bf16.h>
#include <mma.h>

using namespace nvcuda;

#define BB 4
#define NN 4096
#define DIMV 128
#define DE 512
#define TOT (BB * NN)          // 16384 rows
#define CHUNK 16
#define NCHUNK (NN / CHUNK)    // 256

// Scratch (allocation-free: __device__ globals)
__device__ float g_sh[(size_t)TOT * 1024];   // per row: [0,512)=s, [512,1024)=h (raw, post-bias)
__device__ float g_o[(size_t)TOT * DE];      // gated aggregation, input to final GEMM
__device__ float g_part[BB * NCHUNK * DE];   // chunk partial sums -> exclusive offsets

#define SAP 68   // smem pitch (floats)

// ---------------------------------------------------------------------------
// Generic tf32 wmma GEMM:  out[m, j] = sum_k A[m,k] * W[j,k] + bias[j]
// W is row-major [Ntot, K]. Supports a split weight (j >= splitJ uses W1/bias1).
// Tile: 64x64 per block (256 threads, 8 warps of 16x32), BK=64.
// ---------------------------------------------------------------------------
__global__ __launch_bounds__(256) void gemm_tf32_kernel(
    const float* __restrict__ A, int lda,
    const float* __restrict__ W0, const float* __restrict__ bias0,
    const float* __restrict__ W1, const float* __restrict__ bias1,
    int splitJ, int K,
    float* __restrict__ out, int ldo)
{
    __shared__ float sa[64 * SAP];
    __shared__ float sb[64 * SAP];

    const int m0 = blockIdx.x * 64;
    const int j0 = blockIdx.y * 64;

    const float* W = W0;
    const float* bias = bias0;
    int jw = j0;
    if (j0 >= splitJ) { W = W1; bias = bias1; jw = j0 - splitJ; }

    const int tid = threadIdx.x;
    const int warp = tid >> 5;
    const int wm = (warp & 3) * 16;   // warp row offset in tile
    const int wn = (warp >> 2) * 32;  // warp col offset in tile

    wmma::fragment<wmma::accumulator, 16, 16, 8, float> c0, c1;
    wmma::fill_fragment(c0, 0.0f);
    wmma::fill_fragment(c1, 0.0f);

    for (int kb = 0; kb < K; kb += 64) {
        // Load A tile 64x64 (vectorized, coalesced)
        #pragma unroll
        for (int i = 0; i < 4; i++) {
            int idx = tid + i * 256;        // 0..1023 float4 slots
            int r = idx >> 4;               // 0..63
            int c4 = (idx & 15) << 2;       // 0..60 step 4
            float4 v = *reinterpret_cast<const float4*>(
                &A[(size_t)(m0 + r) * lda + kb + c4]);
            *reinterpret_cast<float4*>(&sa[r * SAP + c4]) = v;
        }
        // Load B tile: sb[j][k] = W[(jw+j)*K + kb + k]
        #pragma unroll
        for (int i = 0; i < 4; i++) {
            int idx = tid + i * 256;
            int r = idx >> 4;
            int c4 = (idx & 15) << 2;
            float4 v = *reinterpret_cast<const float4*>(
                &W[(size_t)(jw + r) * K + kb + c4]);
            *reinterpret_cast<float4*>(&sb[r * SAP + c4]) = v;
        }
        __syncthreads();

        #pragma unroll
        for (int kk = 0; kk < 64; kk += 8) {
            wmma::fragment<wmma::matrix_a, 16, 16, 8, wmma::precision::tf32, wmma::row_major> af;
            wmma::fragment<wmma::matrix_b, 16, 16, 8, wmma::precision::tf32, wmma::col_major> bf0, bf1;
            wmma::load_matrix_sync(af, &sa[wm * SAP + kk], SAP);
            wmma::load_matrix_sync(bf0, &sb[wn * SAP + kk], SAP);
            wmma::load_matrix_sync(bf1, &sb[(wn + 16) * SAP + kk], SAP);
            #pragma unroll
            for (int t = 0; t < af.num_elements; t++)  af.x[t]  = wmma::__float_to_tf32(af.x[t]);
            #pragma unroll
            for (int t = 0; t < bf0.num_elements; t++) bf0.x[t] = wmma::__float_to_tf32(bf0.x[t]);
            #pragma unroll
            for (int t = 0; t < bf1.num_elements; t++) bf1.x[t] = wmma::__float_to_tf32(bf1.x[t]);
            wmma::mma_sync(c0, af, bf0, c0);
            wmma::mma_sync(c1, af, bf1, c1);
        }
        __syncthreads();
    }

    // Epilogue: stage through smem, add bias, coalesced global store
    wmma::store_matrix_sync(&sa[wm * SAP + wn],      c0, SAP, wmma::mem_row_major);
    wmma::store_matrix_sync(&sa[wm * SAP + wn + 16], c1, SAP, wmma::mem_row_major);
    __syncthreads();
    #pragma unroll
    for (int i = 0; i < 16; i++) {
        int idx = tid + i * 256;   // 0..4095
        int r = idx >> 6;
        int c = idx & 63;
        out[(size_t)(m0 + r) * ldo + j0 + c] = sa[r * SAP + c] + bias[jw + c];
    }
}

// ---------------------------------------------------------------------------
// Elementwise helpers
// ---------------------------------------------------------------------------
__device__ __forceinline__ float gelu_exact(float x) {
    return 0.5f * x * (1.0f + erff(x * 0.70710678118654752f));
}
__device__ __forceinline__ float sigmoid_f(float x) {
    return 1.0f / (1.0f + expf(-x));
}

// ---------------------------------------------------------------------------
// Pass A: per-chunk sums of the gelu-combined h.
// Thread d in [0,256) handles channel pair (d, d+256):
//   hc_lo = gelu(h[d]),  hc_hi = gelu(h[d]) * gelu(h[d+256])
// ---------------------------------------------------------------------------
__global__ __launch_bounds__(256) void chunk_sum_kernel() {
    const int b  = blockIdx.x / NCHUNK;
    const int ch = blockIdx.x % NCHUNK;
    const int d  = threadIdx.x;  // 0..255

    float s_lo = 0.0f, s_hi = 0.0f;
    size_t base = ((size_t)(b * NN + ch * CHUNK)) * 1024 + 512;
    #pragma unroll 4
    for (int r = 0; r < CHUNK; r++) {
        float x1 = g_sh[base + (size_t)r * 1024 + d];
        float x2 = g_sh[base + (size_t)r * 1024 + 256 + d];
        float g1 = gelu_exact(x1);
        s_lo += g1;
        s_hi += g1 * gelu_exact(x2);
    }
    int pb = (b * NCHUNK + ch) * DE;
    g_part[pb + d]       = s_lo;
    g_part[pb + 256 + d] = s_hi;
}

// ---------------------------------------------------------------------------
// Block-parallel exclusive scan of chunk partials along the chunk axis.
// One 256-thread block per (b, d) pair; threadIdx.x = chunk index.
// ---------------------------------------------------------------------------
__global__ __launch_bounds__(256) void scan_part_kernel() {
    const int b = blockIdx.x / DE;
    const int d = blockIdx.x % DE;
    const int c = threadIdx.x;          // 0..255 == NCHUNK
    const int lane = c & 31;
    const int wid  = c >> 5;

    int idx = (b * NCHUNK + c) * DE + d;
    float v = g_part[idx];

    // warp inclusive scan
    float x = v;
    #pragma unroll
    for (int off = 1; off < 32; off <<= 1) {
        float y = __shfl_up_sync(0xFFFFFFFFu, x, off);
        if (lane >= off) x += y;
    }

    __shared__ float wsum[8];
    if (lane == 31) wsum[wid] = x;
    __syncthreads();

    __shared__ float woff[8];
    if (wid == 0 && lane < 8) {
        float t = wsum[lane];
        #pragma unroll
        for (int off = 1; off < 8; off <<= 1) {
            float y = __shfl_up_sync(0xFFu, t, off);
            if (lane >= off) t += y;
        }
        woff[lane] = t;   // inclusive scan of warp sums
    }
    __syncthreads();

    float base = (wid == 0) ? 0.0f : woff[wid - 1];
    g_part[idx] = base + x - v;   // exclusive prefix
}

// ---------------------------------------------------------------------------
// Pass B: within-chunk inclusive scan with exclusive offset, then
//   o = sigmoid(s) * agg / (m+1 + 1e-7)
// ---------------------------------------------------------------------------
__global__ __launch_bounds__(256) void scan_apply_kernel() {
    const int b  = blockIdx.x / NCHUNK;
    const int ch = blockIdx.x % NCHUNK;
    const int d  = threadIdx.x;  // 0..255

    int pb = (b * NCHUNK + ch) * DE;
    float run_lo = g_part[pb + d];
    float run_hi = g_part[pb + 256 + d];

    #pragma unroll 4
    for (int r = 0; r < CHUNK; r++) {
        int n = ch * CHUNK + r;
        size_t row = (size_t)(b * NN + n);
        float x1 = g_sh[row * 1024 + 512 + d];
        float x2 = g_sh[row * 1024 + 768 + d];
        float g1 = gelu_exact(x1);
        run_lo += g1;
        run_hi += g1 * gelu_exact(x2);

        float rec = 1.0f / ((float)(n + 1) + 1e-7f);
        float s1 = g_sh[row * 1024 + d];
        float s2 = g_sh[row * 1024 + 256 + d];
        g_o[row * DE + d]       = sigmoid_f(s1) * run_lo * rec;
        g_o[row * DE + 256 + d] = sigmoid_f(s2) * run_hi * rec;
    }
}

// ---------------------------------------------------------------------------
// Launcher
// Inputs (metadata order): xq, mask(unused: causal tril by construction),
//                          W_se, b_se, W_po, b_po, W_ag, b_ag
// ---------------------------------------------------------------------------
extern "C" void kernel_launch(void* const* d_in, const int* in_sizes, int n_in,
                              void* d_out, int out_size) {
    const float* xq   = (const float*)d_in[0];
    const float* W_se = (const float*)d_in[2];
    const float* b_se = (const float*)d_in[3];
    const float* W_po = (const float*)d_in[4];
    const float* b_po = (const float*)d_in[5];
    const float* W_ag = (const float*)d_in[6];
    const float* b_ag = (const float*)d_in[7];
    float* out = (float*)d_out;

    float* sh_ptr = nullptr;
    float* o_ptr  = nullptr;
    cudaGetSymbolAddress((void**)&sh_ptr, g_sh);
    cudaGetSymbolAddress((void**)&o_ptr, g_o);

    // GEMM1+2 fused: [16384,128] x [1024,128]^T -> s|h
    {
        dim3 grid(TOT / 64, 1024 / 64);
        gemm_tf32_kernel<<<grid, 256>>>(
            xq, DIMV,
            W_se, b_se, W_po, b_po,
            /*splitJ=*/DE, /*K=*/DIMV,
            sh_ptr, /*ldo=*/1024);
    }

    chunk_sum_kernel<<<BB * NCHUNK, 256>>>();
    scan_part_kernel<<<BB * DE, 256>>>();
    scan_apply_kernel<<<BB * NCHUNK, 256>>>();

    // GEMM3: [16384,512] x [128,512]^T -> out
    {
        dim3 grid(TOT / 64, DIMV / 64);
        gemm_tf32_kernel<<<grid, 256>>>(
            o_ptr, DE,
            W_ag, b_ag, W_ag, b_ag,
            /*splitJ=*/1 << 30, /*K=*/DE,
            out, /*ldo=*/DIMV);
    }
}